// round 2
// baseline (speedup 1.0000x reference)
#include <cuda_runtime.h>
#include <math.h>

// ---------------- problem constants ----------------
#define NB       64
#define C1OUT    256
#define H1       24          // conv1 output 24x24
#define C2OUT    128
#define H2       9           // prim output 9x9
#define NNODES   1296        // 16*81
#define NC       43
#define OD       16
#define CO_TIMES_OD 688      // 43*16
#define CO4      172         // 688/4

// ---------------- device scratch ----------------
__device__ float g_w1t[243 * 256];                 // conv1 weights, [k][co]
__device__ float g_w2t[16384 * 128];               // prim weights,  [k][co]
__device__ float g_h[NB * C1OUT * H1 * H1];        // conv1 output (relu'd)
__device__ float g_u[NB * NNODES * 8];             // primary capsules (squashed in place)
__device__ float g_priors[(size_t)NB * NNODES * CO_TIMES_OD]; // 228MB
__device__ float g_logits[NB * NNODES * NC];
__device__ float g_s[NB * CO_TIMES_OD];
__device__ float g_caps[NB * CO_TIMES_OD];

// ---------------- weight transposes ----------------
__global__ void k_tr1(const float* __restrict__ w) {
    int idx = blockIdx.x * 256 + threadIdx.x;
    if (idx >= 243 * 256) return;
    int k = idx >> 8, co = idx & 255;
    g_w1t[idx] = w[co * 243 + k];
}
__global__ void k_tr2(const float* __restrict__ w) {
    int idx = blockIdx.x * 256 + threadIdx.x;   // 2,097,152 exact
    int k = idx >> 7, co = idx & 127;
    g_w2t[idx] = w[co * 16384 + k];
}

// ---------------- conv1: (64,3,32,32) -> relu(conv 9x9) -> (64,256,24,24) ----------------
__global__ __launch_bounds__(256) void k_conv1(const float* __restrict__ x,
                                               const float* __restrict__ bias) {
    int oy = blockIdx.x, b = blockIdx.y, co = threadIdx.x;
    __shared__ float xs[3 * 9 * 32];   // input rows oy..oy+8, 3 channels
    for (int idx = co; idx < 864; idx += 256) {
        int ci = idx / 288, rem = idx - ci * 288;
        int r = rem >> 5, col = rem & 31;
        xs[idx] = x[((b * 3 + ci) * 32 + oy + r) * 32 + col];
    }
    __syncthreads();
    float acc[24];
    float bv = bias[co];
#pragma unroll
    for (int i = 0; i < 24; i++) acc[i] = bv;
    for (int ci = 0; ci < 3; ci++) {
        for (int ky = 0; ky < 9; ky++) {
            float in[32];
#pragma unroll
            for (int c2 = 0; c2 < 32; c2++) in[c2] = xs[ci * 288 + ky * 32 + c2];
#pragma unroll
            for (int kx = 0; kx < 9; kx++) {
                float w = g_w1t[(ci * 81 + ky * 9 + kx) * 256 + co];
#pragma unroll
                for (int ox = 0; ox < 24; ox++)
                    acc[ox] = fmaf(in[ox + kx], w, acc[ox]);
            }
        }
    }
    float* hp = &g_h[((b * 256 + co) * 24 + oy) * 24];
#pragma unroll
    for (int ox = 0; ox < 24; ox++) hp[ox] = fmaxf(acc[ox], 0.f);
}

// ---------------- prim conv: (64,256,24,24) -> conv 8x8 s2 -> caps layout (pre-squash) ----------------
__global__ __launch_bounds__(256) void k_prim(const float* __restrict__ bias) {
    int oy = blockIdx.x, b = blockIdx.y;
    int tid = threadIdx.x;
    int kh = tid >> 7;          // k-range half
    int co = tid & 127;
    __shared__ float hs[64 * 8 * 24];   // 48KB: one 64-channel chunk of the input window
    float acc[9];
#pragma unroll
    for (int i = 0; i < 9; i++) acc[i] = 0.f;

    for (int cc = 0; cc < 4; cc++) {
        __syncthreads();
        for (int idx = tid; idx < 12288; idx += 256) {
            int ci = idx / 192, rem = idx - ci * 192;
            int r = rem / 24, col = rem - r * 24;
            hs[idx] = g_h[((b * 256 + cc * 64 + ci) * 24 + 2 * oy + r) * 24 + col];
        }
        __syncthreads();
        int ci0 = kh * 32;
        for (int cil = ci0; cil < ci0 + 32; cil++) {
            const float* hrow = &hs[cil * 192];
            for (int ky = 0; ky < 8; ky++) {
                float in[24];
#pragma unroll
                for (int c2 = 0; c2 < 24; c2++) in[c2] = hrow[ky * 24 + c2];
                const float* wp = &g_w2t[(((cc * 64 + cil) * 8 + ky) * 8) * 128 + co];
#pragma unroll
                for (int kx = 0; kx < 8; kx++) {
                    float w = wp[kx * 128];
#pragma unroll
                    for (int ox = 0; ox < 9; ox++)
                        acc[ox] = fmaf(in[2 * ox + kx], w, acc[ox]);
                }
            }
        }
    }
    __syncthreads();
    if (kh == 1) {
#pragma unroll
        for (int ox = 0; ox < 9; ox++) hs[co * 9 + ox] = acc[ox];
    }
    __syncthreads();
    if (kh == 0) {
        float bv = bias[co];
        int i = co >> 4, g = co & 15;
#pragma unroll
        for (int ox = 0; ox < 9; ox++) {
            float v = acc[ox] + hs[co * 9 + ox] + bv;
            int n = g * 81 + oy * 9 + ox;
            g_u[(b * NNODES + n) * 8 + i] = v;
        }
    }
}

// ---------------- squash primary capsules (dim 8, in place) ----------------
__global__ void k_squash_u() {
    int node = blockIdx.x * 256 + threadIdx.x;
    if (node >= NB * NNODES) return;
    float v[8]; float sn = 0.f;
#pragma unroll
    for (int i = 0; i < 8; i++) { v[i] = g_u[node * 8 + i]; sn = fmaf(v[i], v[i], sn); }
    float f = sqrtf(sn) / (1.f + sn);
#pragma unroll
    for (int i = 0; i < 8; i++) g_u[node * 8 + i] = v[i] * f;
}

// ---------------- priors[b,n,c,o] = sum_i u[b,n,i] * W[n,c,i,o] ----------------
__global__ __launch_bounds__(256) void k_priors(const float* __restrict__ route_w) {
    int n = blockIdx.x, tid = threadIdx.x;
    __shared__ float rw[NC * 8 * OD];   // 5504
    __shared__ float us[NB * 8];        // 512
    for (int idx = tid; idx < 5504; idx += 256) rw[idx] = route_w[n * 5504 + idx];
    for (int idx = tid; idx < 512; idx += 256) {
        int b = idx >> 3, i = idx & 7;
        us[idx] = g_u[(b * NNODES + n) * 8 + i];
    }
    __syncthreads();
    if (tid < CO4) {
        int c = tid >> 2;
        int obase = (tid & 3) * 4;
        const float* rwc = &rw[c * 128 + obase];
        float4* out4 = reinterpret_cast<float4*>(g_priors);
        for (int b = 0; b < NB; b++) {
            const float* ub = &us[b * 8];
            float4 sum = make_float4(0.f, 0.f, 0.f, 0.f);
#pragma unroll
            for (int i = 0; i < 8; i++) {
                float u = ub[i];
                sum.x = fmaf(u, rwc[i * 16 + 0], sum.x);
                sum.y = fmaf(u, rwc[i * 16 + 1], sum.y);
                sum.z = fmaf(u, rwc[i * 16 + 2], sum.z);
                sum.w = fmaf(u, rwc[i * 16 + 3], sum.w);
            }
            out4[(size_t)(b * NNODES + n) * CO4 + tid] = sum;
        }
    }
}

// ---------------- zero helpers ----------------
__global__ void k_zero_s() {
    int i = blockIdx.x * 256 + threadIdx.x;
    if (i < NB * CO_TIMES_OD) g_s[i] = 0.f;
}
__global__ void k_zero_logits() {
    int i = blockIdx.x * 256 + threadIdx.x;
    if (i < NB * NNODES * NC) g_logits[i] = 0.f;
}

// ---------------- iter0: s = sum_n priors (uniform probs folded into squash scale) ----------------
__global__ __launch_bounds__(256) void k_reduce0() {
    int b = blockIdx.y, n0 = blockIdx.x * 81, tid = threadIdx.x;
    if (tid >= CO4) return;
    const float4* pri4 = reinterpret_cast<const float4*>(g_priors);
    float4 acc = make_float4(0.f, 0.f, 0.f, 0.f);
    for (int nn = 0; nn < 81; nn++) {
        float4 p = pri4[(size_t)(b * NNODES + n0 + nn) * CO4 + tid];
        acc.x += p.x; acc.y += p.y; acc.z += p.z; acc.w += p.w;
    }
    float* sp = &g_s[b * CO_TIMES_OD + tid * 4];
    atomicAdd(sp + 0, acc.x); atomicAdd(sp + 1, acc.y);
    atomicAdd(sp + 2, acc.z); atomicAdd(sp + 3, acc.w);
}

// ---------------- squash s -> output capsules ----------------
__global__ void k_squash_out(float scale) {
    int idx = blockIdx.x * 256 + threadIdx.x;
    if (idx >= NB * NC) return;
    float v[16]; float sn = 0.f;
#pragma unroll
    for (int o = 0; o < 16; o++) { v[o] = g_s[idx * 16 + o] * scale; sn = fmaf(v[o], v[o], sn); }
    float f = sqrtf(sn) / (1.f + sn);
#pragma unroll
    for (int o = 0; o < 16; o++) g_caps[idx * 16 + o] = v[o] * f;
}

// ---------------- routing iteration: delta -> logits -> softmax -> s accumulate ----------------
__global__ __launch_bounds__(256) void k_iter() {
    int b = blockIdx.y, n0 = blockIdx.x * 16, tid = threadIdx.x;
    __shared__ float dsum[48];
    __shared__ float probs[64];
    if (tid >= 43 && tid < 64) probs[tid] = 0.f;

    const float4* pri4 = reinterpret_cast<const float4*>(g_priors);
    const float4* caps4 = reinterpret_cast<const float4*>(g_caps);
    float4 outs = make_float4(0.f, 0.f, 0.f, 0.f);
    if (tid < CO4) outs = caps4[b * CO4 + tid];
    float4 acc = make_float4(0.f, 0.f, 0.f, 0.f);

    for (int nn = 0; nn < 16; nn++) {
        int n = n0 + nn;
        float4 pr = make_float4(0.f, 0.f, 0.f, 0.f);
        if (tid < CO4) pr = pri4[(size_t)(b * NNODES + n) * CO4 + tid];
        // delta_c = sum_o priors * outputs  (4 lanes per class, reduce width 4)
        float t = pr.x * outs.x + pr.y * outs.y + pr.z * outs.z + pr.w * outs.w;
        t += __shfl_xor_sync(0xffffffffu, t, 2, 4);
        t += __shfl_xor_sync(0xffffffffu, t, 1, 4);
        if (tid < CO4 && (tid & 3) == 0) dsum[tid >> 2] = t;
        __syncthreads();
        if (tid < 32) {
            int c1 = tid, c2 = tid + 32;
            int L = (b * NNODES + n) * NC;
            float l1 = (c1 < NC) ? g_logits[L + c1] + dsum[c1] : -1e30f;
            float l2 = (c2 < NC) ? g_logits[L + c2] + dsum[c2] : -1e30f;
            if (c1 < NC) g_logits[L + c1] = l1;
            if (c2 < NC) g_logits[L + c2] = l2;
            float m = fmaxf(l1, l2);
#pragma unroll
            for (int off = 16; off; off >>= 1) m = fmaxf(m, __shfl_xor_sync(0xffffffffu, m, off));
            float e1 = (c1 < NC) ? __expf(l1 - m) : 0.f;
            float e2 = (c2 < NC) ? __expf(l2 - m) : 0.f;
            float ss = e1 + e2;
#pragma unroll
            for (int off = 16; off; off >>= 1) ss += __shfl_xor_sync(0xffffffffu, ss, off);
            float inv = 1.f / ss;
            if (c1 < NC) probs[c1] = e1 * inv;
            if (c2 < NC) probs[c2] = e2 * inv;
        }
        __syncthreads();
        float p = probs[tid >> 2];
        acc.x = fmaf(p, pr.x, acc.x); acc.y = fmaf(p, pr.y, acc.y);
        acc.z = fmaf(p, pr.z, acc.z); acc.w = fmaf(p, pr.w, acc.w);
    }
    if (tid < CO4) {
        float* sp = &g_s[b * CO_TIMES_OD + tid * 4];
        atomicAdd(sp + 0, acc.x); atomicAdd(sp + 1, acc.y);
        atomicAdd(sp + 2, acc.z); atomicAdd(sp + 3, acc.w);
    }
}

// ---------------- final: scores = ||squash(s)|| = sn/(1+sn) ----------------
__global__ void k_final(float* __restrict__ out) {
    int idx = blockIdx.x * 256 + threadIdx.x;
    if (idx >= NB * NC) return;
    float sn = 0.f;
#pragma unroll
    for (int o = 0; o < 16; o++) { float v = g_s[idx * 16 + o]; sn = fmaf(v, v, sn); }
    out[idx] = sn / (1.f + sn);
}

// ---------------- launch ----------------
extern "C" void kernel_launch(void* const* d_in, const int* in_sizes, int n_in,
                              void* d_out, int out_size) {
    const float* x  = (const float*)d_in[0];
    const float* w1 = (const float*)d_in[1];
    const float* b1 = (const float*)d_in[2];
    const float* w2 = (const float*)d_in[3];
    const float* b2 = (const float*)d_in[4];
    const float* rw = (const float*)d_in[5];
    float* out = (float*)d_out;

    k_tr1<<<243, 256>>>(w1);
    k_tr2<<<8192, 256>>>(w2);
    k_conv1<<<dim3(24, NB), 256>>>(x, b1);
    k_prim<<<dim3(9, NB), 256>>>(b2);
    k_squash_u<<<(NB * NNODES + 255) / 256, 256>>>();
    k_priors<<<NNODES, 256>>>(rw);

    // iter 0: uniform probs (1/43 folded into squash scale)
    k_zero_s<<<172, 256>>>();
    k_reduce0<<<dim3(16, NB), 256>>>();
    k_squash_out<<<11, 256>>>(1.f / 43.f);

    // iter 1
    k_zero_logits<<<(NB * NNODES * NC + 255) / 256, 256>>>();
    k_zero_s<<<172, 256>>>();
    k_iter<<<dim3(81, NB), 256>>>();
    k_squash_out<<<11, 256>>>(1.f);

    // iter 2 (final)
    k_zero_s<<<172, 256>>>();
    k_iter<<<dim3(81, NB), 256>>>();
    k_final<<<11, 256>>>(out);
}